// round 14
// baseline (speedup 1.0000x reference)
#include <cuda_runtime.h>
#include <cstdint>

#define Bb 8
#define Tt 1024
#define Uu 1024
#define Hh 8
#define Dd 128
#define NEGB  -6.0e9f    /* log2-domain "-inf" */
#define QSC   (0.08838834764831845f * 1.44269504088896341f)  /* 1/sqrt(128) * log2(e) */

// ---------------- scratch (static device memory; no allocations) ----------------
__device__ uint16_t g_Abf[3][Bb * Tt * Uu];      // bf16 inputs
__device__ uint16_t g_WTbf[3][Uu * Uu];          // bf16 W^T [n][k]
__device__ uint16_t g_Qbf[Bb * Tt * Uu];         // bf16 Q, pre-scaled by QSC
__device__ uint16_t g_Kbf[Bb * Tt * Uu];         // bf16 K
__device__ uint16_t g_Vtbf[Bb * Hh * Dd * Tt];   // bf16 V^T per (b,h): [d][token]
__device__ float g_AO[Bb * Tt * Uu];
__device__ float g_qmask[Bb * Tt];               // 1/0
__device__ float g_kbias[Bb * Tt];               // 0 or NEGB

// ================= helpers =======================================================
__device__ __forceinline__ uint32_t packbf(float lo, float hi) {
    uint32_t r;
    asm("cvt.rn.bf16x2.f32 %0, %1, %2;" : "=r"(r) : "f"(hi), "f"(lo));
    return r;
}
__device__ __forceinline__ float ex2(float x) {
    float r;
    asm("ex2.approx.ftz.f32 %0, %1;" : "=f"(r) : "f"(x));
    return r;
}
__device__ __forceinline__ void mma16n8k16(float* d, const uint32_t* a, const uint32_t* b) {
    asm volatile(
        "mma.sync.aligned.m16n8k16.row.col.f32.bf16.bf16.f32 "
        "{%0,%1,%2,%3}, {%4,%5,%6,%7}, {%8,%9}, {%0,%1,%2,%3};"
        : "+f"(d[0]), "+f"(d[1]), "+f"(d[2]), "+f"(d[3])
        : "r"(a[0]), "r"(a[1]), "r"(a[2]), "r"(a[3]), "r"(b[0]), "r"(b[1]));
}
__device__ __forceinline__ void cp16(void* s, const void* g) {
    uint32_t sa = (uint32_t)__cvta_generic_to_shared(s);
    asm volatile("cp.async.cg.shared.global [%0], [%1], 16;" :: "r"(sa), "l"(g) : "memory");
}
__device__ __forceinline__ void ldsm4(uint32_t& r0, uint32_t& r1, uint32_t& r2,
                                      uint32_t& r3, uint32_t addr) {
    asm volatile("ldmatrix.sync.aligned.m8n8.x4.shared.b16 {%0,%1,%2,%3}, [%4];"
                 : "=r"(r0), "=r"(r1), "=r"(r2), "=r"(r3) : "r"(addr));
}
__device__ __forceinline__ uint32_t sptr(const void* p) {
    return (uint32_t)__cvta_generic_to_shared(p);
}
#define CP_COMMIT() asm volatile("cp.async.commit_group;" ::: "memory")
#define CP_WAIT0()  asm volatile("cp.async.wait_group 0;" ::: "memory")
#define CP_WAIT1()  asm volatile("cp.async.wait_group 1;" ::: "memory")

// ldmatrix lane address patterns
#define AROW(l) (((l) & 7) + ((((l) >> 3) & 1) << 3))
#define ACOL(l) ((((l) >> 4) & 1) * 4)
#define BROW(l) (((l) & 7) + (((l) >> 4) << 3))
#define BCOL(l) ((((l) >> 3) & 1) * 4)

// ---------------- input convert + row masks --------------------------------------
__global__ void __launch_bounds__(256) a_convert(
    const float* __restrict__ q, const float* __restrict__ k, const float* __restrict__ v) {
    __shared__ float red[8];
    const int y = blockIdx.y, row = blockIdx.x, tid = threadIdx.x;
    const float* src = (y == 0) ? q : (y == 1) ? k : v;
    float4 val = ((const float4*)(src + (size_t)row * 1024))[tid];
    uint2 p = { packbf(val.x, val.y), packbf(val.z, val.w) };
    ((uint2*)(g_Abf[y] + (size_t)row * 1024))[tid] = p;
    if (y < 2) {
        float s = val.x + val.y + val.z + val.w;
#pragma unroll
        for (int off = 16; off; off >>= 1) s += __shfl_xor_sync(0xffffffffu, s, off);
        if ((tid & 31) == 0) red[tid >> 5] = s;
        __syncthreads();
        if (tid == 0) {
            float t = 0.f;
#pragma unroll
            for (int w = 0; w < 8; w++) t += red[w];
            if (y == 0) g_qmask[row] = (t != 0.0f) ? 1.0f : 0.0f;
            else        g_kbias[row] = (t != 0.0f) ? 0.0f : NEGB;
        }
    }
}

// ---------------- W transpose + convert: W[k][n] fp32 -> WT[n][k] bf16 -----------
__global__ void __launch_bounds__(256) w_convert(
    const float* __restrict__ Wq, const float* __restrict__ Wk,
    const float* __restrict__ Wv) {
    __shared__ float t[32][33];
    const int which = blockIdx.z;
    const float* W = (which == 0) ? Wq : (which == 1) ? Wk : Wv;
    uint16_t* WT = g_WTbf[which];
    const int x0 = blockIdx.x * 32, y0 = blockIdx.y * 32;  // x: n, y: k
    const int tx = threadIdx.x & 31, ty = threadIdx.x >> 5;
#pragma unroll
    for (int r = ty; r < 32; r += 8)
        t[r][tx] = W[(size_t)(y0 + r) * Uu + x0 + tx];
    __syncthreads();
    const int wt = threadIdx.x & 15, rn0 = threadIdx.x >> 4;
#pragma unroll
    for (int rr = 0; rr < 2; rr++) {
        const int rn = rn0 + rr * 16;
        uint32_t pw = packbf(t[2 * wt][rn], t[2 * wt + 1][rn]);
        *(uint32_t*)(WT + (size_t)(x0 + rn) * Uu + y0 + 2 * wt) = pw;
    }
}

// ---------------- bf16 mma GEMM, 3-stage cp.async pipeline + ldmatrix ------------
#define KB2 64
#define AW 36
#define HALF_ST (128 * AW * 4)          /* 18432: one operand tile */
#define STB (2 * HALF_ST)               /* 36864: A+B per stage */
#define NSTAGE 3
#define GEMM_SMEM (NSTAGE * STB)        /* 110592 */
#define NKB (Uu / KB2)                  /* 16 */

__global__ void __launch_bounds__(256, 2) gemm_bf16_kernel(
    const float* __restrict__ bi0, const float* __restrict__ bi1,
    const float* __restrict__ bi2) {
    extern __shared__ __align__(16) char gsm[];

    const int which = blockIdx.z;
    const uint16_t* Abf  = g_Abf[which];
    const uint16_t* WTbf = g_WTbf[which];
    const float* bias = (which == 0) ? bi0 : (which == 1) ? bi1 : bi2;

    const int tid = threadIdx.x;
    const int warp = tid >> 5, lane = tid & 31;
    const int g = lane >> 2, t = lane & 3;
    const int warpM = (warp >> 2) * 64, warpN = (warp & 3) * 32;
    const int n0 = blockIdx.x * 128, m0 = blockIdx.y * 128;

    const int arow = AROW(lane), acol = ACOL(lane);
    const int brow = BROW(lane), bcol = BCOL(lane);

    float acc[4][4][4] = {};

    auto load_tiles = [&](int kb, int st) {
        uint32_t (*As)[AW] = reinterpret_cast<uint32_t(*)[AW]>(gsm + st * STB);
        uint32_t (*Bs)[AW] = reinterpret_cast<uint32_t(*)[AW]>(gsm + st * STB + HALF_ST);
#pragma unroll
        for (int i = 0; i < 4; i++) {
            const int idx = tid + i * 256;
            const int r = idx >> 3, s = idx & 7;
            cp16(&As[r][s * 4], Abf + (size_t)(m0 + r) * Uu + kb + s * 8);
        }
#pragma unroll
        for (int i = 0; i < 4; i++) {
            const int idx = tid + i * 256;
            const int r = idx >> 3, s = idx & 7;
            cp16(&Bs[r][s * 4], WTbf + (size_t)(n0 + r) * Uu + kb + s * 8);
        }
        CP_COMMIT();
    };

    // prologue: 2 stages in flight
    load_tiles(0, 0);
    load_tiles(KB2, 1);

#pragma unroll 1
    for (int it = 0; it < NKB; ++it) {
        const int st = it % NSTAGE;
        if (it + 1 < NKB) CP_WAIT1(); else CP_WAIT0();
        __syncthreads();
        if (it + 2 < NKB) load_tiles((it + 2) * KB2, (it + 2) % NSTAGE);

        const uint32_t abase = sptr(gsm + st * STB) +
                               (warpM + arow) * (AW * 4) + acol * 4;
        const uint32_t bbase = sptr(gsm + st * STB + HALF_ST) +
                               (warpN + brow) * (AW * 4) + bcol * 4;
#pragma unroll
        for (int ks = 0; ks < 4; ks++) {
            uint32_t af[4][4], bf[4][2];
#pragma unroll
            for (int mi = 0; mi < 4; mi++)
                ldsm4(af[mi][0], af[mi][1], af[mi][2], af[mi][3],
                      abase + mi * (16 * AW * 4) + ks * 32);
#pragma unroll
            for (int n2 = 0; n2 < 2; n2++)
                ldsm4(bf[2 * n2][0], bf[2 * n2][1], bf[2 * n2 + 1][0], bf[2 * n2 + 1][1],
                      bbase + n2 * (16 * AW * 4) + ks * 32);
#pragma unroll
            for (int mi = 0; mi < 4; mi++)
#pragma unroll
                for (int ni = 0; ni < 4; ni++)
                    mma16n8k16(acc[mi][ni], af[mi], bf[ni]);
        }
    }
    __syncthreads();   // all compute done before epilogue may reuse gsm (V path)

    if (which != 2) {
        uint16_t* C = (which == 0) ? g_Qbf : g_Kbf;
        const float osc = (which == 0) ? QSC : 1.0f;   // Q pre-scaled for log2 softmax
#pragma unroll
        for (int mi = 0; mi < 4; mi++) {
            const int r0 = m0 + warpM + mi * 16 + g;
#pragma unroll
            for (int ni = 0; ni < 4; ni++) {
                const int cc = n0 + warpN + ni * 8 + 2 * t;
                const float b0 = bias[cc], b1 = bias[cc + 1];
                uint32_t p0 = packbf(fmaxf(acc[mi][ni][0] + b0, 0.0f) * osc,
                                     fmaxf(acc[mi][ni][1] + b1, 0.0f) * osc);
                uint32_t p1 = packbf(fmaxf(acc[mi][ni][2] + b0, 0.0f) * osc,
                                     fmaxf(acc[mi][ni][3] + b1, 0.0f) * osc);
                *(uint32_t*)(C + (size_t)r0 * Uu + cc)       = p0;
                *(uint32_t*)(C + (size_t)(r0 + 8) * Uu + cc) = p1;
            }
        }
    } else {
        float (*tile)[132] = reinterpret_cast<float(*)[132]>(gsm);
#pragma unroll
        for (int mi = 0; mi < 4; mi++) {
            const int rl = warpM + mi * 16 + g;
#pragma unroll
            for (int ni = 0; ni < 4; ni++) {
                const int cl = warpN + ni * 8 + 2 * t;
                const float b0 = bias[n0 + cl], b1 = bias[n0 + cl + 1];
                tile[cl][rl]         = fmaxf(acc[mi][ni][0] + b0, 0.0f);
                tile[cl + 1][rl]     = fmaxf(acc[mi][ni][1] + b1, 0.0f);
                tile[cl][rl + 8]     = fmaxf(acc[mi][ni][2] + b0, 0.0f);
                tile[cl + 1][rl + 8] = fmaxf(acc[mi][ni][3] + b1, 0.0f);
            }
        }
        __syncthreads();
        const int bq = m0 >> 10, tok0 = m0 & 1023, hh = n0 >> 7;
        uint16_t* base = g_Vtbf + (((size_t)bq * Hh + hh) * Dd) * Tt + tok0;
#pragma unroll
        for (int i = 0; i < 8; i++) {
            const int idx = tid + i * 256;
            const int r = idx >> 4, seg = idx & 15;
            float4 a = *(float4*)&tile[r][seg * 8];
            float4 c = *(float4*)&tile[r][seg * 8 + 4];
            uint4 o = { packbf(a.x, a.y), packbf(a.z, a.w),
                        packbf(c.x, c.y), packbf(c.z, c.w) };
            *(uint4*)(base + (size_t)r * Tt + seg * 8) = o;
        }
    }
}

// ---------------- flash attention: bf16 mma + ldmatrix, 128-key chunks -----------
// Q tile 64 x 128; K/V chunks of 128 keys, single-buffered each, two-group FIFO.
// Softmax runs ONCE per 128 keys (half the fixed cost of 64-key chunks).
#define QW 68   /* K/Q word pitch: d=128 -> 64 words + 4 pad */
#define VW2 68  /* Vt word pitch: keys=128 -> 64 words + 4 pad */
struct ASmem {
    uint32_t Qs[64][QW];          // 17408 B
    uint32_t Ks[128][QW];         // 34816 B
    uint32_t Vts[128][VW2];       // 34816 B  [d][key]
    float kb[128];                // 512 B
};                                 // 87,552 B -> 2 CTAs/SM

__global__ void __launch_bounds__(128, 2) attn_kernel() {
    extern __shared__ char raw[];
    ASmem& sm = *(ASmem*)raw;
    const int qt = gridDim.x - 1 - blockIdx.x;   // long-first scheduling
    const int b = blockIdx.y, h = blockIdx.z;
    const int tid = threadIdx.x;
    const int warp = tid >> 5, lane = tid & 31;
    const int g = lane >> 2, t = lane & 3;

    const uint16_t* Qg  = g_Qbf + ((size_t)b * Tt + qt * 64) * Uu + h * Dd;
    const uint16_t* Kg  = g_Kbf + (size_t)b * Tt * Uu + h * Dd;
    const uint16_t* Vtg = g_Vtbf + ((size_t)b * Hh + h) * Dd * Tt;
    const float* kbg = g_kbias + b * Tt;

    const int arow = AROW(lane), acol = ACOL(lane);
    const int brow = BROW(lane), bcol = BCOL(lane);

    // group A: K(kt) + kb(kt);  group B: V(kt)
    auto load_k = [&](int kt) {
#pragma unroll
        for (int i = 0; i < 16; i++) {
            const int idx = tid + i * 128;
            const int r = idx >> 4, s = idx & 15;
            cp16(&sm.Ks[r][s * 4], Kg + (size_t)(kt * 128 + r) * Uu + s * 8);
        }
        if (tid < 32) cp16(&sm.kb[tid * 4], kbg + kt * 128 + tid * 4);
        CP_COMMIT();
    };
    auto load_v = [&](int kt) {
#pragma unroll
        for (int i = 0; i < 16; i++) {
            const int idx = tid + i * 128;
            const int r = idx >> 4, s = idx & 15;
            cp16(&sm.Vts[r][s * 4], Vtg + (size_t)r * Tt + kt * 128 + s * 8);
        }
        CP_COMMIT();
    };

    // prologue: {Q + K0 + kb0} group, then {V0} group
#pragma unroll
    for (int i = 0; i < 8; i++) {
        const int idx = tid + i * 128;
        const int r = idx >> 4, s = idx & 15;
        cp16(&sm.Qs[r][s * 4], Qg + (size_t)r * Uu + s * 8);
    }
    load_k(0);
    load_v(0);
    CP_WAIT1();          // Q/K0/kb0 landed (V0 may still fly)
    __syncthreads();

    // hoist Q fragments via ldmatrix (8 ks x 4 regs)
    uint32_t qf[8][4];
    {
        const uint32_t qbase = sptr(&sm.Qs[16 * warp + arow][acol]);
#pragma unroll
        for (int ks = 0; ks < 8; ks++)
            ldsm4(qf[ks][0], qf[ks][1], qf[ks][2], qf[ks][3], qbase + ks * 32);
    }

    float oacc[16][4] = {};
    float mrow0 = NEGB, mrow1 = NEGB, lrow0 = 0.0f, lrow1 = 0.0f;
    const int qrow0 = qt * 64 + 16 * warp + g;
    const int ktmax = qt >> 1;           // 128-key chunks

    for (int kt = 0; kt <= ktmax; kt++) {
        // S = Q K^T : 16 rows x 128 keys (8 ks x 16 ni)
        float sc[16][4] = {};
        {
            const uint32_t kbase = sptr(&sm.Ks[brow][bcol]);
#pragma unroll
            for (int ks = 0; ks < 8; ks++) {
#pragma unroll
                for (int n2 = 0; n2 < 8; n2++) {
                    uint32_t b0, b1, b2, b3;
                    ldsm4(b0, b1, b2, b3, kbase + n2 * (16 * QW * 4) + ks * 32);
                    uint32_t bfA[2] = { b0, b1 };
                    uint32_t bfB[2] = { b2, b3 };
                    mma16n8k16(sc[2 * n2],     qf[ks], bfA);
                    mma16n8k16(sc[2 * n2 + 1], qf[ks], bfB);
                }
            }
        }
        __syncthreads();                         // Ks consumed by all warps
        if (kt < ktmax) load_k(kt + 1);          // group A_{kt+1}

        // bias + (last-chunk-only) causal + row max
        float mx0 = NEGB, mx1 = NEGB;
        if (kt < ktmax) {
#pragma unroll
            for (int ni = 0; ni < 16; ni++) {
                const float b0 = sm.kb[8 * ni + 2 * t];
                const float b1 = sm.kb[8 * ni + 2 * t + 1];
                sc[ni][0] += b0; sc[ni][1] += b1;
                sc[ni][2] += b0; sc[ni][3] += b1;
                mx0 = fmaxf(mx0, fmaxf(sc[ni][0], sc[ni][1]));
                mx1 = fmaxf(mx1, fmaxf(sc[ni][2], sc[ni][3]));
            }
        } else {
#pragma unroll
            for (int ni = 0; ni < 16; ni++) {
                const int kk = kt * 128 + 8 * ni + 2 * t;
                const float b0 = sm.kb[8 * ni + 2 * t];
                const float b1 = sm.kb[8 * ni + 2 * t + 1];
                float v0 = sc[ni][0] + b0; if (kk     > qrow0)     v0 = NEGB;
                float v1 = sc[ni][1] + b1; if (kk + 1 > qrow0)     v1 = NEGB;
                float v2 = sc[ni][2] + b0; if (kk     > qrow0 + 8) v2 = NEGB;
                float v3 = sc[ni][3] + b1; if (kk + 1 > qrow0 + 8) v3 = NEGB;
                sc[ni][0] = v0; sc[ni][1] = v1; sc[ni][2] = v2; sc[ni][3] = v3;
                mx0 = fmaxf(mx0, fmaxf(v0, v1));
                mx1 = fmaxf(mx1, fmaxf(v2, v3));
            }
        }
        mx0 = fmaxf(mx0, __shfl_xor_sync(0xffffffffu, mx0, 1));
        mx0 = fmaxf(mx0, __shfl_xor_sync(0xffffffffu, mx0, 2));
        mx1 = fmaxf(mx1, __shfl_xor_sync(0xffffffffu, mx1, 1));
        mx1 = fmaxf(mx1, __shfl_xor_sync(0xffffffffu, mx1, 2));

        const float mn0 = fmaxf(mrow0, mx0), mn1 = fmaxf(mrow1, mx1);
        const float al0 = ex2(mrow0 - mn0), al1 = ex2(mrow1 - mn1);
        float ps0 = 0.0f, ps1 = 0.0f;
        uint32_t pp[16][2];                  // P in registers = PV A-fragments
#pragma unroll
        for (int ni = 0; ni < 16; ni++) {
            float p0 = ex2(sc[ni][0] - mn0);
            float p1 = ex2(sc[ni][1] - mn0);
            float p2 = ex2(sc[ni][2] - mn1);
            float p3 = ex2(sc[ni][3] - mn1);
            ps0 += p0 + p1; ps1 += p2 + p3;
            pp[ni][0] = packbf(p0, p1);
            pp[ni][1] = packbf(p2, p3);
        }
        ps0 += __shfl_xor_sync(0xffffffffu, ps0, 1);
        ps0 += __shfl_xor_sync(0xffffffffu, ps0, 2);
        ps1 += __shfl_xor_sync(0xffffffffu, ps1, 1);
        ps1 += __shfl_xor_sync(0xffffffffu, ps1, 2);
        lrow0 = lrow0 * al0 + ps0;
        lrow1 = lrow1 * al1 + ps1;
        mrow0 = mn0; mrow1 = mn1;
#pragma unroll
        for (int ni = 0; ni < 16; ni++) {
            oacc[ni][0] *= al0; oacc[ni][1] *= al0;
            oacc[ni][2] *= al1; oacc[ni][3] *= al1;
        }

        // V(kt) landed?  FIFO: group B_kt older than A_{kt+1}
        if (kt < ktmax) CP_WAIT1(); else CP_WAIT0();
        __syncthreads();

        // O += P @ V : k-dim = 128 keys (8 ks of 16), d = 128 (16 ni)
        {
            const uint32_t vbase = sptr(&sm.Vts[brow][bcol]);
#pragma unroll
            for (int ks = 0; ks < 8; ks++) {
                uint32_t af[4] = { pp[2 * ks][0], pp[2 * ks][1],
                                   pp[2 * ks + 1][0], pp[2 * ks + 1][1] };
#pragma unroll
                for (int n2 = 0; n2 < 8; n2++) {
                    uint32_t b0, b1, b2, b3;
                    ldsm4(b0, b1, b2, b3, vbase + n2 * (16 * VW2 * 4) + ks * 32);
                    uint32_t bfA[2] = { b0, b1 };
                    uint32_t bfB[2] = { b2, b3 };
                    mma16n8k16(oacc[2 * n2],     af, bfA);
                    mma16n8k16(oacc[2 * n2 + 1], af, bfB);
                }
            }
        }
        __syncthreads();                         // Vts consumed

        if (kt < ktmax) {
            load_v(kt + 1);                      // group B_{kt+1}
            CP_WAIT1();                          // A_{kt+1} (K) done, FIFO
            __syncthreads();
        }
    }

    // normalize, query mask, store
    const float inv0 = g_qmask[b * Tt + qrow0] / lrow0;
    const float inv1 = g_qmask[b * Tt + qrow0 + 8] / lrow1;
    float* AOg = g_AO + ((size_t)b * Tt + qrow0) * Uu + h * Dd;
#pragma unroll
    for (int ni = 0; ni < 16; ni++) {
        const int cc = 8 * ni + 2 * t;
        float2 o0, o1;
        o0.x = oacc[ni][0] * inv0; o0.y = oacc[ni][1] * inv0;
        o1.x = oacc[ni][2] * inv1; o1.y = oacc[ni][3] * inv1;
        *(float2*)(AOg + cc)                  = o0;
        *(float2*)(AOg + (size_t)8 * Uu + cc) = o1;
    }
}

// ---------------- residual + LayerNorm ------------------------------------------
__global__ void __launch_bounds__(256) ln_kernel(
    const float* __restrict__ Qin, const float* __restrict__ gamma,
    const float* __restrict__ beta, float* __restrict__ out) {
    __shared__ float red[2][8];
    const int row = blockIdx.x, tid = threadIdx.x;
    float4 a = ((const float4*)(g_AO + (size_t)row * 1024))[tid];
    float4 q = ((const float4*)(Qin + (size_t)row * 1024))[tid];
    float4 x;
    x.x = a.x + q.x; x.y = a.y + q.y; x.z = a.z + q.z; x.w = a.w + q.w;
    float s  = x.x + x.y + x.z + x.w;
    float ss = x.x * x.x + x.y * x.y + x.z * x.z + x.w * x.w;
#pragma unroll
    for (int off = 16; off; off >>= 1) {
        s  += __shfl_xor_sync(0xffffffffu, s, off);
        ss += __shfl_xor_sync(0xffffffffu, ss, off);
    }
    if ((tid & 31) == 0) { red[0][tid >> 5] = s; red[1][tid >> 5] = ss; }
    __syncthreads();
    s = 0.f; ss = 0.f;
#pragma unroll
    for (int w = 0; w < 8; w++) { s += red[0][w]; ss += red[1][w]; }
    const float mu = s * (1.0f / 1024.0f);
    const float var = ss * (1.0f / 1024.0f) - mu * mu;
    const float rstd = rsqrtf(var + 1e-5f);
    float4 g  = ((const float4*)gamma)[tid];
    float4 be = ((const float4*)beta)[tid];
    float4 o;
    o.x = (x.x - mu) * rstd * g.x + be.x;
    o.y = (x.y - mu) * rstd * g.y + be.y;
    o.z = (x.z - mu) * rstd * g.z + be.z;
    o.w = (x.w - mu) * rstd * g.w + be.w;
    ((float4*)(out + (size_t)row * 1024))[tid] = o;
}

// ---------------- launch ---------------------------------------------------------
extern "C" void kernel_launch(void* const* d_in, const int* in_sizes, int n_in,
                              void* d_out, int out_size) {
    const float* queries = (const float*)d_in[0];
    const float* keys    = (const float*)d_in[1];
    const float* values  = (const float*)d_in[2];
    const float* Wq = (const float*)d_in[3];
    const float* bq = (const float*)d_in[4];
    const float* Wk = (const float*)d_in[5];
    const float* bk = (const float*)d_in[6];
    const float* Wv = (const float*)d_in[7];
    const float* bv = (const float*)d_in[8];
    const float* gamma = (const float*)d_in[9];
    const float* beta  = (const float*)d_in[10];
    float* out = (float*)d_out;

    cudaFuncSetAttribute(attn_kernel, cudaFuncAttributeMaxDynamicSharedMemorySize,
                         (int)sizeof(ASmem));
    cudaFuncSetAttribute(gemm_bf16_kernel, cudaFuncAttributeMaxDynamicSharedMemorySize,
                         GEMM_SMEM);

    w_convert<<<dim3(32, 32, 3), 256>>>(Wq, Wk, Wv);
    a_convert<<<dim3(Bb * Tt, 3), 256>>>(queries, keys, values);

    gemm_bf16_kernel<<<dim3(8, 64, 3), 256, GEMM_SMEM>>>(bq, bk, bv);

    attn_kernel<<<dim3(Tt / 64, Bb, Hh), 128, sizeof(ASmem)>>>();

    ln_kernel<<<Bb * Tt, 256>>>(queries, gamma, beta, out);
}

// round 15
// speedup vs baseline: 1.0573x; 1.0573x over previous
#include <cuda_runtime.h>
#include <cstdint>

#define Bb 8
#define Tt 1024
#define Uu 1024
#define Hh 8
#define Dd 128
#define NEGB  -6.0e9f    /* log2-domain "-inf" */
#define QSC   (0.08838834764831845f * 1.44269504088896341f)  /* 1/sqrt(128) * log2(e) */

// ---------------- scratch (static device memory; no allocations) ----------------
__device__ uint16_t g_Abf[3][Bb * Tt * Uu];      // bf16 inputs
__device__ uint16_t g_WTbf[3][Uu * Uu];          // bf16 W^T [n][k]
__device__ uint16_t g_Qbf[Bb * Tt * Uu];         // bf16 Q, pre-scaled by QSC
__device__ uint16_t g_Kbf[Bb * Tt * Uu];         // bf16 K
__device__ uint16_t g_Vtbf[Bb * Hh * Dd * Tt];   // bf16 V^T per (b,h): [d][token]
__device__ float g_AO[Bb * Tt * Uu];
__device__ float g_qmask[Bb * Tt];               // 1/0
__device__ float g_kbias[Bb * Tt];               // 0 or NEGB

// ================= helpers =======================================================
__device__ __forceinline__ uint32_t packbf(float lo, float hi) {
    uint32_t r;
    asm("cvt.rn.bf16x2.f32 %0, %1, %2;" : "=r"(r) : "f"(hi), "f"(lo));
    return r;
}
__device__ __forceinline__ float ex2(float x) {
    float r;
    asm("ex2.approx.ftz.f32 %0, %1;" : "=f"(r) : "f"(x));
    return r;
}
// packed dual multiply: (a0*s, a1*s) — identical RN rounding, one issue slot
__device__ __forceinline__ void mul2(float& a0, float& a1, uint64_t s2) {
    uint64_t a;
    asm("mov.b64 %0, {%1, %2};" : "=l"(a) : "f"(a0), "f"(a1));
    asm("mul.rn.f32x2 %0, %0, %1;" : "+l"(a) : "l"(s2));
    asm("mov.b64 {%0, %1}, %2;" : "=f"(a0), "=f"(a1) : "l"(a));
}
__device__ __forceinline__ void mma16n8k16(float* d, const uint32_t* a, const uint32_t* b) {
    asm volatile(
        "mma.sync.aligned.m16n8k16.row.col.f32.bf16.bf16.f32 "
        "{%0,%1,%2,%3}, {%4,%5,%6,%7}, {%8,%9}, {%0,%1,%2,%3};"
        : "+f"(d[0]), "+f"(d[1]), "+f"(d[2]), "+f"(d[3])
        : "r"(a[0]), "r"(a[1]), "r"(a[2]), "r"(a[3]), "r"(b[0]), "r"(b[1]));
}
__device__ __forceinline__ void cp16(void* s, const void* g) {
    uint32_t sa = (uint32_t)__cvta_generic_to_shared(s);
    asm volatile("cp.async.cg.shared.global [%0], [%1], 16;" :: "r"(sa), "l"(g) : "memory");
}
__device__ __forceinline__ void ldsm4(uint32_t& r0, uint32_t& r1, uint32_t& r2,
                                      uint32_t& r3, uint32_t addr) {
    asm volatile("ldmatrix.sync.aligned.m8n8.x4.shared.b16 {%0,%1,%2,%3}, [%4];"
                 : "=r"(r0), "=r"(r1), "=r"(r2), "=r"(r3) : "r"(addr));
}
__device__ __forceinline__ uint32_t sptr(const void* p) {
    return (uint32_t)__cvta_generic_to_shared(p);
}
#define CP_COMMIT() asm volatile("cp.async.commit_group;" ::: "memory")
#define CP_WAIT0()  asm volatile("cp.async.wait_group 0;" ::: "memory")
#define CP_WAIT1()  asm volatile("cp.async.wait_group 1;" ::: "memory")

// ldmatrix lane address patterns
#define AROW(l) (((l) & 7) + ((((l) >> 3) & 1) << 3))
#define ACOL(l) ((((l) >> 4) & 1) * 4)
#define BROW(l) (((l) & 7) + (((l) >> 4) << 3))
#define BCOL(l) ((((l) >> 3) & 1) * 4)

// ---------------- input convert + row masks --------------------------------------
__global__ void __launch_bounds__(256) a_convert(
    const float* __restrict__ q, const float* __restrict__ k, const float* __restrict__ v) {
    __shared__ float red[8];
    const int y = blockIdx.y, row = blockIdx.x, tid = threadIdx.x;
    const float* src = (y == 0) ? q : (y == 1) ? k : v;
    float4 val = ((const float4*)(src + (size_t)row * 1024))[tid];
    uint2 p = { packbf(val.x, val.y), packbf(val.z, val.w) };
    ((uint2*)(g_Abf[y] + (size_t)row * 1024))[tid] = p;
    if (y < 2) {
        float s = val.x + val.y + val.z + val.w;
#pragma unroll
        for (int off = 16; off; off >>= 1) s += __shfl_xor_sync(0xffffffffu, s, off);
        if ((tid & 31) == 0) red[tid >> 5] = s;
        __syncthreads();
        if (tid == 0) {
            float t = 0.f;
#pragma unroll
            for (int w = 0; w < 8; w++) t += red[w];
            if (y == 0) g_qmask[row] = (t != 0.0f) ? 1.0f : 0.0f;
            else        g_kbias[row] = (t != 0.0f) ? 0.0f : NEGB;
        }
    }
}

// ---------------- W transpose + convert: W[k][n] fp32 -> WT[n][k] bf16 -----------
__global__ void __launch_bounds__(256) w_convert(
    const float* __restrict__ Wq, const float* __restrict__ Wk,
    const float* __restrict__ Wv) {
    __shared__ float t[32][33];
    const int which = blockIdx.z;
    const float* W = (which == 0) ? Wq : (which == 1) ? Wk : Wv;
    uint16_t* WT = g_WTbf[which];
    const int x0 = blockIdx.x * 32, y0 = blockIdx.y * 32;  // x: n, y: k
    const int tx = threadIdx.x & 31, ty = threadIdx.x >> 5;
#pragma unroll
    for (int r = ty; r < 32; r += 8)
        t[r][tx] = W[(size_t)(y0 + r) * Uu + x0 + tx];
    __syncthreads();
    const int wt = threadIdx.x & 15, rn0 = threadIdx.x >> 4;
#pragma unroll
    for (int rr = 0; rr < 2; rr++) {
        const int rn = rn0 + rr * 16;
        uint32_t pw = packbf(t[2 * wt][rn], t[2 * wt + 1][rn]);
        *(uint32_t*)(WT + (size_t)(x0 + rn) * Uu + y0 + 2 * wt) = pw;
    }
}

// ---------------- bf16 mma GEMM, 3-stage cp.async pipeline + ldmatrix ------------
#define KB2 64
#define AW 36
#define HALF_ST (128 * AW * 4)          /* 18432: one operand tile */
#define STB (2 * HALF_ST)               /* 36864: A+B per stage */
#define NSTAGE 3
#define GEMM_SMEM (NSTAGE * STB)        /* 110592 */
#define NKB (Uu / KB2)                  /* 16 */

__global__ void __launch_bounds__(256, 2) gemm_bf16_kernel(
    const float* __restrict__ bi0, const float* __restrict__ bi1,
    const float* __restrict__ bi2) {
    extern __shared__ __align__(16) char gsm[];

    const int which = blockIdx.z;
    const uint16_t* Abf  = g_Abf[which];
    const uint16_t* WTbf = g_WTbf[which];
    const float* bias = (which == 0) ? bi0 : (which == 1) ? bi1 : bi2;

    const int tid = threadIdx.x;
    const int warp = tid >> 5, lane = tid & 31;
    const int g = lane >> 2, t = lane & 3;
    const int warpM = (warp >> 2) * 64, warpN = (warp & 3) * 32;
    const int n0 = blockIdx.x * 128, m0 = blockIdx.y * 128;

    const int arow = AROW(lane), acol = ACOL(lane);
    const int brow = BROW(lane), bcol = BCOL(lane);

    float acc[4][4][4] = {};

    auto load_tiles = [&](int kb, int st) {
        uint32_t (*As)[AW] = reinterpret_cast<uint32_t(*)[AW]>(gsm + st * STB);
        uint32_t (*Bs)[AW] = reinterpret_cast<uint32_t(*)[AW]>(gsm + st * STB + HALF_ST);
#pragma unroll
        for (int i = 0; i < 4; i++) {
            const int idx = tid + i * 256;
            const int r = idx >> 3, s = idx & 7;
            cp16(&As[r][s * 4], Abf + (size_t)(m0 + r) * Uu + kb + s * 8);
        }
#pragma unroll
        for (int i = 0; i < 4; i++) {
            const int idx = tid + i * 256;
            const int r = idx >> 3, s = idx & 7;
            cp16(&Bs[r][s * 4], WTbf + (size_t)(n0 + r) * Uu + kb + s * 8);
        }
        CP_COMMIT();
    };

    // prologue: 2 stages in flight
    load_tiles(0, 0);
    load_tiles(KB2, 1);

#pragma unroll 1
    for (int it = 0; it < NKB; ++it) {
        const int st = it % NSTAGE;
        if (it + 1 < NKB) CP_WAIT1(); else CP_WAIT0();
        __syncthreads();
        if (it + 2 < NKB) load_tiles((it + 2) * KB2, (it + 2) % NSTAGE);

        const uint32_t abase = sptr(gsm + st * STB) +
                               (warpM + arow) * (AW * 4) + acol * 4;
        const uint32_t bbase = sptr(gsm + st * STB + HALF_ST) +
                               (warpN + brow) * (AW * 4) + bcol * 4;
#pragma unroll
        for (int ks = 0; ks < 4; ks++) {
            uint32_t af[4][4], bf[4][2];
#pragma unroll
            for (int mi = 0; mi < 4; mi++)
                ldsm4(af[mi][0], af[mi][1], af[mi][2], af[mi][3],
                      abase + mi * (16 * AW * 4) + ks * 32);
#pragma unroll
            for (int n2 = 0; n2 < 2; n2++)
                ldsm4(bf[2 * n2][0], bf[2 * n2][1], bf[2 * n2 + 1][0], bf[2 * n2 + 1][1],
                      bbase + n2 * (16 * AW * 4) + ks * 32);
#pragma unroll
            for (int mi = 0; mi < 4; mi++)
#pragma unroll
                for (int ni = 0; ni < 4; ni++)
                    mma16n8k16(acc[mi][ni], af[mi], bf[ni]);
        }
    }
    __syncthreads();   // all compute done before epilogue may reuse gsm (V path)

    if (which != 2) {
        uint16_t* C = (which == 0) ? g_Qbf : g_Kbf;
        const float osc = (which == 0) ? QSC : 1.0f;   // Q pre-scaled for log2 softmax
#pragma unroll
        for (int mi = 0; mi < 4; mi++) {
            const int r0 = m0 + warpM + mi * 16 + g;
#pragma unroll
            for (int ni = 0; ni < 4; ni++) {
                const int cc = n0 + warpN + ni * 8 + 2 * t;
                const float b0 = bias[cc], b1 = bias[cc + 1];
                uint32_t p0 = packbf(fmaxf(acc[mi][ni][0] + b0, 0.0f) * osc,
                                     fmaxf(acc[mi][ni][1] + b1, 0.0f) * osc);
                uint32_t p1 = packbf(fmaxf(acc[mi][ni][2] + b0, 0.0f) * osc,
                                     fmaxf(acc[mi][ni][3] + b1, 0.0f) * osc);
                *(uint32_t*)(C + (size_t)r0 * Uu + cc)       = p0;
                *(uint32_t*)(C + (size_t)(r0 + 8) * Uu + cc) = p1;
            }
        }
    } else {
        float (*tile)[132] = reinterpret_cast<float(*)[132]>(gsm);
#pragma unroll
        for (int mi = 0; mi < 4; mi++) {
            const int rl = warpM + mi * 16 + g;
#pragma unroll
            for (int ni = 0; ni < 4; ni++) {
                const int cl = warpN + ni * 8 + 2 * t;
                const float b0 = bias[n0 + cl], b1 = bias[n0 + cl + 1];
                tile[cl][rl]         = fmaxf(acc[mi][ni][0] + b0, 0.0f);
                tile[cl + 1][rl]     = fmaxf(acc[mi][ni][1] + b1, 0.0f);
                tile[cl][rl + 8]     = fmaxf(acc[mi][ni][2] + b0, 0.0f);
                tile[cl + 1][rl + 8] = fmaxf(acc[mi][ni][3] + b1, 0.0f);
            }
        }
        __syncthreads();
        const int bq = m0 >> 10, tok0 = m0 & 1023, hh = n0 >> 7;
        uint16_t* base = g_Vtbf + (((size_t)bq * Hh + hh) * Dd) * Tt + tok0;
#pragma unroll
        for (int i = 0; i < 8; i++) {
            const int idx = tid + i * 256;
            const int r = idx >> 4, seg = idx & 15;
            float4 a = *(float4*)&tile[r][seg * 8];
            float4 c = *(float4*)&tile[r][seg * 8 + 4];
            uint4 o = { packbf(a.x, a.y), packbf(a.z, a.w),
                        packbf(c.x, c.y), packbf(c.z, c.w) };
            *(uint4*)(base + (size_t)r * Tt + seg * 8) = o;
        }
    }
}

// ---------------- flash attention: bf16 mma + ldmatrix, double-buffered ----------
// R12 configuration (measured 90.2us): 64-key chunks, K/V double-buffered, one
// rendezvous per iter, P in registers, log2 softmax. f32x2 packed oacc rescale.
#define QW 68   /* word pitch (%32==4 -> conflict-free ldmatrix phases) */
#define VW 36
struct ASmem {
    uint32_t Qs[64][QW];          // 17408 B
    uint32_t Ks[2][64][QW];       // 34816 B
    uint32_t Vts[2][128][VW];     // 36864 B  [d][key]
    float kb[2][64];              // 512 B
};                                 // 89,600 B -> 2 CTAs/SM

__global__ void __launch_bounds__(128, 2) attn_kernel() {
    extern __shared__ char raw[];
    ASmem& sm = *(ASmem*)raw;
    const int qt = gridDim.x - 1 - blockIdx.x;   // long-first scheduling
    const int b = blockIdx.y, h = blockIdx.z;
    const int tid = threadIdx.x;
    const int warp = tid >> 5, lane = tid & 31;
    const int g = lane >> 2, t = lane & 3;

    const uint16_t* Qg  = g_Qbf + ((size_t)b * Tt + qt * 64) * Uu + h * Dd;
    const uint16_t* Kg  = g_Kbf + (size_t)b * Tt * Uu + h * Dd;
    const uint16_t* Vtg = g_Vtbf + ((size_t)b * Hh + h) * Dd * Tt;
    const float* kbg = g_kbias + b * Tt;

    const int arow = AROW(lane), acol = ACOL(lane);
    const int brow = BROW(lane), bcol = BCOL(lane);

    auto load_kv = [&](int kt, int buf) {
#pragma unroll
        for (int i = 0; i < 8; i++) {
            const int idx = tid + i * 128;
            const int r = idx >> 4, s = idx & 15;
            cp16(&sm.Ks[buf][r][s * 4], Kg + (size_t)(kt * 64 + r) * Uu + s * 8);
        }
#pragma unroll
        for (int i = 0; i < 8; i++) {
            const int idx = tid + i * 128;
            const int r = idx >> 3, s = idx & 7;
            cp16(&sm.Vts[buf][r][s * 4], Vtg + (size_t)r * Tt + kt * 64 + s * 8);
        }
        if (tid < 16) cp16(&sm.kb[buf][tid * 4], kbg + kt * 64 + tid * 4);
        CP_COMMIT();
    };

    // prologue: Q + chunk 0 in one group
#pragma unroll
    for (int i = 0; i < 8; i++) {
        const int idx = tid + i * 128;
        const int r = idx >> 4, s = idx & 15;
        cp16(&sm.Qs[r][s * 4], Qg + (size_t)r * Uu + s * 8);
    }
    load_kv(0, 0);
    CP_WAIT0();
    __syncthreads();

    // hoist Q fragments via ldmatrix (8 ks x 4 regs)
    uint32_t qf[8][4];
    {
        const uint32_t qbase = sptr(&sm.Qs[16 * warp + arow][acol]);
#pragma unroll
        for (int ks = 0; ks < 8; ks++)
            ldsm4(qf[ks][0], qf[ks][1], qf[ks][2], qf[ks][3], qbase + ks * 32);
    }

    float oacc[16][4] = {};
    float mrow0 = NEGB, mrow1 = NEGB, lrow0 = 0.0f, lrow1 = 0.0f;
    const int qrow0 = qt * 64 + 16 * warp + g;
    const int ktmax = qt;

    for (int kt = 0; kt <= ktmax; kt++) {
        const int buf = kt & 1;

        if (kt < ktmax) load_kv(kt + 1, buf ^ 1);

        // S = Q K^T via ldmatrix B-frags
        float sc[8][4] = {};
        {
            const uint32_t kbase = sptr(&sm.Ks[buf][brow][bcol]);
#pragma unroll
            for (int ks = 0; ks < 8; ks++) {
#pragma unroll
                for (int n2 = 0; n2 < 4; n2++) {
                    uint32_t b0, b1, b2, b3;
                    ldsm4(b0, b1, b2, b3, kbase + n2 * (16 * QW * 4) + ks * 32);
                    uint32_t bfA[2] = { b0, b1 };
                    uint32_t bfB[2] = { b2, b3 };
                    mma16n8k16(sc[2 * n2],     qf[ks], bfA);
                    mma16n8k16(sc[2 * n2 + 1], qf[ks], bfB);
                }
            }
        }

        // bias + (diagonal-only) causal + row max
        float mx0 = NEGB, mx1 = NEGB;
        if (kt < ktmax) {
#pragma unroll
            for (int ni = 0; ni < 8; ni++) {
                const float b0 = sm.kb[buf][8 * ni + 2 * t];
                const float b1 = sm.kb[buf][8 * ni + 2 * t + 1];
                sc[ni][0] += b0; sc[ni][1] += b1;
                sc[ni][2] += b0; sc[ni][3] += b1;
                mx0 = fmaxf(mx0, fmaxf(sc[ni][0], sc[ni][1]));
                mx1 = fmaxf(mx1, fmaxf(sc[ni][2], sc[ni][3]));
            }
        } else {
#pragma unroll
            for (int ni = 0; ni < 8; ni++) {
                const int kk = kt * 64 + 8 * ni + 2 * t;
                const float b0 = sm.kb[buf][8 * ni + 2 * t];
                const float b1 = sm.kb[buf][8 * ni + 2 * t + 1];
                float v0 = sc[ni][0] + b0; if (kk     > qrow0)     v0 = NEGB;
                float v1 = sc[ni][1] + b1; if (kk + 1 > qrow0)     v1 = NEGB;
                float v2 = sc[ni][2] + b0; if (kk     > qrow0 + 8) v2 = NEGB;
                float v3 = sc[ni][3] + b1; if (kk + 1 > qrow0 + 8) v3 = NEGB;
                sc[ni][0] = v0; sc[ni][1] = v1; sc[ni][2] = v2; sc[ni][3] = v3;
                mx0 = fmaxf(mx0, fmaxf(v0, v1));
                mx1 = fmaxf(mx1, fmaxf(v2, v3));
            }
        }
        mx0 = fmaxf(mx0, __shfl_xor_sync(0xffffffffu, mx0, 1));
        mx0 = fmaxf(mx0, __shfl_xor_sync(0xffffffffu, mx0, 2));
        mx1 = fmaxf(mx1, __shfl_xor_sync(0xffffffffu, mx1, 1));
        mx1 = fmaxf(mx1, __shfl_xor_sync(0xffffffffu, mx1, 2));

        const float mn0 = fmaxf(mrow0, mx0), mn1 = fmaxf(mrow1, mx1);
        const float al0 = ex2(mrow0 - mn0), al1 = ex2(mrow1 - mn1);
        float ps0 = 0.0f, ps1 = 0.0f;
        uint32_t pp[8][2];                  // P in registers = PV A-fragments
#pragma unroll
        for (int ni = 0; ni < 8; ni++) {
            float p0 = ex2(sc[ni][0] - mn0);
            float p1 = ex2(sc[ni][1] - mn0);
            float p2 = ex2(sc[ni][2] - mn1);
            float p3 = ex2(sc[ni][3] - mn1);
            ps0 += p0 + p1; ps1 += p2 + p3;
            pp[ni][0] = packbf(p0, p1);
            pp[ni][1] = packbf(p2, p3);
        }
        ps0 += __shfl_xor_sync(0xffffffffu, ps0, 1);
        ps0 += __shfl_xor_sync(0xffffffffu, ps0, 2);
        ps1 += __shfl_xor_sync(0xffffffffu, ps1, 1);
        ps1 += __shfl_xor_sync(0xffffffffu, ps1, 2);
        lrow0 = lrow0 * al0 + ps0;
        lrow1 = lrow1 * al1 + ps1;
        mrow0 = mn0; mrow1 = mn1;
        // packed rescale: (al0,al0) on regs 0,1 and (al1,al1) on regs 2,3
        {
            uint64_t s0, s1;
            asm("mov.b64 %0, {%1, %1};" : "=l"(s0) : "f"(al0));
            asm("mov.b64 %0, {%1, %1};" : "=l"(s1) : "f"(al1));
#pragma unroll
            for (int ni = 0; ni < 16; ni++) {
                mul2(oacc[ni][0], oacc[ni][1], s0);
                mul2(oacc[ni][2], oacc[ni][3], s1);
            }
        }

        // O += P @ V via ldmatrix B-frags
        {
            const uint32_t vbase = sptr(&sm.Vts[buf][brow][bcol]);
#pragma unroll
            for (int ks = 0; ks < 4; ks++) {
                uint32_t af[4] = { pp[2 * ks][0], pp[2 * ks][1],
                                   pp[2 * ks + 1][0], pp[2 * ks + 1][1] };
#pragma unroll
                for (int n2 = 0; n2 < 8; n2++) {
                    uint32_t b0, b1, b2, b3;
                    ldsm4(b0, b1, b2, b3, vbase + n2 * (16 * VW * 4) + ks * 32);
                    uint32_t bfA[2] = { b0, b1 };
                    uint32_t bfB[2] = { b2, b3 };
                    mma16n8k16(oacc[2 * n2],     af, bfA);
                    mma16n8k16(oacc[2 * n2 + 1], af, bfB);
                }
            }
        }

        if (kt < ktmax) {
            CP_WAIT0();
            __syncthreads();
        }
    }

    // normalize, query mask, store
    const float inv0 = g_qmask[b * Tt + qrow0] / lrow0;
    const float inv1 = g_qmask[b * Tt + qrow0 + 8] / lrow1;
    float* AOg = g_AO + ((size_t)b * Tt + qrow0) * Uu + h * Dd;
#pragma unroll
    for (int ni = 0; ni < 16; ni++) {
        const int cc = 8 * ni + 2 * t;
        float2 o0, o1;
        o0.x = oacc[ni][0] * inv0; o0.y = oacc[ni][1] * inv0;
        o1.x = oacc[ni][2] * inv1; o1.y = oacc[ni][3] * inv1;
        *(float2*)(AOg + cc)                  = o0;
        *(float2*)(AOg + (size_t)8 * Uu + cc) = o1;
    }
}

// ---------------- residual + LayerNorm ------------------------------------------
__global__ void __launch_bounds__(256) ln_kernel(
    const float* __restrict__ Qin, const float* __restrict__ gamma,
    const float* __restrict__ beta, float* __restrict__ out) {
    __shared__ float red[2][8];
    const int row = blockIdx.x, tid = threadIdx.x;
    float4 a = ((const float4*)(g_AO + (size_t)row * 1024))[tid];
    float4 q = ((const float4*)(Qin + (size_t)row * 1024))[tid];
    float4 x;
    x.x = a.x + q.x; x.y = a.y + q.y; x.z = a.z + q.z; x.w = a.w + q.w;
    float s  = x.x + x.y + x.z + x.w;
    float ss = x.x * x.x + x.y * x.y + x.z * x.z + x.w * x.w;
#pragma unroll
    for (int off = 16; off; off >>= 1) {
        s  += __shfl_xor_sync(0xffffffffu, s, off);
        ss += __shfl_xor_sync(0xffffffffu, ss, off);
    }
    if ((tid & 31) == 0) { red[0][tid >> 5] = s; red[1][tid >> 5] = ss; }
    __syncthreads();
    s = 0.f; ss = 0.f;
#pragma unroll
    for (int w = 0; w < 8; w++) { s += red[0][w]; ss += red[1][w]; }
    const float mu = s * (1.0f / 1024.0f);
    const float var = ss * (1.0f / 1024.0f) - mu * mu;
    const float rstd = rsqrtf(var + 1e-5f);
    float4 g  = ((const float4*)gamma)[tid];
    float4 be = ((const float4*)beta)[tid];
    float4 o;
    o.x = (x.x - mu) * rstd * g.x + be.x;
    o.y = (x.y - mu) * rstd * g.y + be.y;
    o.z = (x.z - mu) * rstd * g.z + be.z;
    o.w = (x.w - mu) * rstd * g.w + be.w;
    ((float4*)(out + (size_t)row * 1024))[tid] = o;
}

// ---------------- launch ---------------------------------------------------------
extern "C" void kernel_launch(void* const* d_in, const int* in_sizes, int n_in,
                              void* d_out, int out_size) {
    const float* queries = (const float*)d_in[0];
    const float* keys    = (const float*)d_in[1];
    const float* values  = (const float*)d_in[2];
    const float* Wq = (const float*)d_in[3];
    const float* bq = (const float*)d_in[4];
    const float* Wk = (const float*)d_in[5];
    const float* bk = (const float*)d_in[6];
    const float* Wv = (const float*)d_in[7];
    const float* bv = (const float*)d_in[8];
    const float* gamma = (const float*)d_in[9];
    const float* beta  = (const float*)d_in[10];
    float* out = (float*)d_out;

    cudaFuncSetAttribute(attn_kernel, cudaFuncAttributeMaxDynamicSharedMemorySize,
                         (int)sizeof(ASmem));
    cudaFuncSetAttribute(gemm_bf16_kernel, cudaFuncAttributeMaxDynamicSharedMemorySize,
                         GEMM_SMEM);

    w_convert<<<dim3(32, 32, 3), 256>>>(Wq, Wk, Wv);
    a_convert<<<dim3(Bb * Tt, 3), 256>>>(queries, keys, values);

    gemm_bf16_kernel<<<dim3(8, 64, 3), 256, GEMM_SMEM>>>(bq, bk, bv);

    attn_kernel<<<dim3(Tt / 64, Bb, Hh), 128, sizeof(ASmem)>>>();

    ln_kernel<<<Bb * Tt, 256>>>(queries, gamma, beta, out);
}